// round 5
// baseline (speedup 1.0000x reference)
#include <cuda_runtime.h>

// Fixed problem shape.
#define BB 8
#define QQ 900
#define KK 1203
#define NN 100
#define KPAD 1216                 // row stride in smem floats (16B aligned)
#define WARPS 5
#define THREADS (WARPS * 32)      // 160
#define RPW 4                     // rows per warp
#define WPB_BATCH 225             // warps per batch (900/4)
#define BLKX 45                   // 225 / 5

// cost[b,q,n] = 2*focal_cls + 5*L1 - 2*GIoU
// Warp-private row streaming: each warp stages logits row (coalesced float4)
// into its own smem slice, selects 100 labeled columns via LDS. No block
// barrier in the hot loop; warps loop over 4 rows each.
__global__ void __launch_bounds__(THREADS, 8) matcher_cost_kernel(
    const float*  __restrict__ logits,   // (B,Q,K)
    const float4* __restrict__ pboxes,   // (B,Q,4)
    const int*    __restrict__ labels,   // (B,N)
    const float4* __restrict__ tboxes,   // (B,N,4)
    float* __restrict__ out)             // (B,Q,N)
{
    __shared__ float  s_rows[WARPS][KPAD];   // 24,320 B
    __shared__ float4 s_tb[NN];              // cxcywh
    __shared__ float4 s_txy[NN];             // xyxy
    __shared__ float  s_ta[NN];              // areas
    __shared__ int    s_lab[NN];             // clamped labels

    const int b    = blockIdx.y;
    const int tid  = threadIdx.x;
    const int w    = tid >> 5;
    const int lane = tid & 31;

    // ---- stage per-batch target data (once per block) ----
    if (tid < NN) {
        int l = labels[b * NN + tid];
        s_lab[tid] = min(max(l, 0), KK - 1);
        float4 tb = tboxes[b * NN + tid];
        s_tb[tid] = tb;
        float4 xy;
        xy.x = tb.x - 0.5f * tb.z;
        xy.y = tb.y - 0.5f * tb.w;
        xy.z = tb.x + 0.5f * tb.z;
        xy.w = tb.y + 0.5f * tb.w;
        s_txy[tid] = xy;
        s_ta[tid]  = tb.z * tb.w;
    }
    __syncthreads();   // the only block-wide barrier

    const int wb = blockIdx.x * WARPS + w;   // warp index within batch [0,225)
    float* const sbuf = s_rows[w];

    #pragma unroll 1
    for (int r = 0; r < RPW; r++) {
        const int q   = wb * RPW + r;        // row within batch
        const int row = b * QQ + q;          // global row

        // ---- stage row q: coalesced float4 stream into warp-private smem ----
        {
            const long E = (long)row * KK;
            const float* src = logits + E;
            const int head = (4 - ((int)E & 3)) & 3;   // floats to 16B align
            if (lane < head) sbuf[lane] = src[lane];
            const float4* vsrc = (const float4*)(src + head);
            #pragma unroll
            for (int i = 0; i < 10; i++) {
                int idx = lane + i * 32;
                if (idx < 300) {                        // (KK-head)>>2 == 300
                    float4 v = vsrc[idx];
                    int o = head + idx * 4;
                    sbuf[o]     = v.x;
                    sbuf[o + 1] = v.y;
                    sbuf[o + 2] = v.z;
                    sbuf[o + 3] = v.w;
                }
            }
            const int done = head + 1200;
            if (lane < KK - done) sbuf[done + lane] = src[done + lane];
        }

        // pred box (warp-uniform; issued alongside the stream)
        const float4 pb = pboxes[row];
        const float px0 = pb.x - 0.5f * pb.z, px1 = pb.x + 0.5f * pb.z;
        const float py0 = pb.y - 0.5f * pb.w, py1 = pb.y + 0.5f * pb.w;
        const float area1 = pb.z * pb.w;
        float* const orow = out + (long)row * NN;

        __syncwarp();

        // ---- 100 outputs: lane handles n = lane, +32, +64, +96 ----
        #pragma unroll
        for (int i = 0; i < 4; i++) {
            int n = lane + i * 32;
            if (n < NN) {
                float x = sbuf[s_lab[n]];     // LDS select

                // focal class cost (3 MUFU)
                float e  = __expf(-x);
                float s  = 1.0f + e;
                float p  = __fdividef(1.0f, s);
                float L  = __logf(s);
                float logp   = fmaxf(-L,     -18.420681f);
                float log1mp = fmaxf(-x - L, -18.420681f);
                float omp = 1.0f - p;
                float cls = -0.25f * omp * omp * logp + 0.75f * p * p * log1mp;

                // L1 box cost
                float4 tb = s_tb[n];
                float l1 = fabsf(pb.x - tb.x) + fabsf(pb.y - tb.y)
                         + fabsf(pb.z - tb.z) + fabsf(pb.w - tb.w);

                // GIoU (1 MUFU)
                float4 xy = s_txy[n];
                float area2 = s_ta[n];
                float wi = fmaxf(fminf(px1, xy.z) - fmaxf(px0, xy.x), 0.0f);
                float hi = fmaxf(fminf(py1, xy.w) - fmaxf(py0, xy.y), 0.0f);
                float inter = wi * hi;
                float uni   = area1 + area2 - inter;
                float wc = fmaxf(px1, xy.z) - fminf(px0, xy.x);
                float hc = fmaxf(py1, xy.w) - fminf(py0, xy.y);
                float ac = wc * hc;
                float num  = ac * (inter - uni) + uni * uni;
                float giou = num * __fdividef(1.0f, uni * ac);

                orow[n] = 2.0f * cls + 5.0f * l1 - 2.0f * giou;
            }
        }

        __syncwarp();   // all lanes done reading sbuf before next stage
    }
}

extern "C" void kernel_launch(void* const* d_in, const int* in_sizes, int n_in,
                              void* d_out, int out_size)
{
    const float*  logits = (const float*)d_in[0];
    const float4* pboxes = (const float4*)d_in[1];
    const int*    labels = (const int*)d_in[2];
    const float4* tboxes = (const float4*)d_in[3];
    float* out = (float*)d_out;

    dim3 grid(BLKX, BB);   // (45, 8) = 360 blocks, 5 warps each, 4 rows/warp
    matcher_cost_kernel<<<grid, THREADS>>>(logits, pboxes, labels, tboxes, out);
}

// round 6
// speedup vs baseline: 1.7022x; 1.7022x over previous
#include <cuda_runtime.h>
#include <cstdint>

// Fixed problem shape.
#define BB 8
#define QQ 900
#define KK 1203
#define NN 100
#define ROW_BYTES (KK * 4)        // 4812
#define BUF_FLOATS 1216           // 4864 B buffer (head + 4832 max copy fits)
#define WARPS 4
#define THREADS (WARPS * 32)
#define RPW 4                     // rows per warp (4 | 900 -> never straddles batch)
#define TOTAL_WARPS (BB * QQ / RPW)   // 1800
#define BLOCKS (TOTAL_WARPS / WARPS)  // 450

__device__ __forceinline__ uint32_t smem_u32(const void* p) {
    uint32_t a;
    asm("{ .reg .u64 t; cvta.to.shared.u64 t, %1; cvt.u32.u64 %0, t; }" : "=r"(a) : "l"(p));
    return a;
}

__device__ __forceinline__ void mbar_init(uint32_t mbar, uint32_t count) {
    asm volatile("mbarrier.init.shared.b64 [%0], %1;" :: "r"(mbar), "r"(count) : "memory");
}

__device__ __forceinline__ void issue_row_copy(uint32_t sbuf, const char* gbase,
                                               long row, uint32_t mbar) {
    long base    = row * (long)ROW_BYTES;
    long aligned = base & ~15L;
    int  head    = (int)(base & 15L);            // 0,12,8,4
    int  size    = (ROW_BYTES + head + 15) & ~15; // <= 4832
    asm volatile("mbarrier.arrive.expect_tx.shared.b64 _, [%0], %1;"
                 :: "r"(mbar), "r"(size) : "memory");
    asm volatile("cp.async.bulk.shared::cta.global.mbarrier::complete_tx::bytes "
                 "[%0], [%1], %2, [%3];"
                 :: "r"(sbuf), "l"(gbase + aligned), "r"(size), "r"(mbar) : "memory");
}

__device__ __forceinline__ void mbar_wait(uint32_t mbar, uint32_t parity) {
    uint32_t done;
    asm volatile(
        "{\n\t.reg .pred p;\n\t"
        "mbarrier.try_wait.parity.acquire.cta.shared::cta.b64 p, [%1], %2;\n\t"
        "selp.b32 %0, 1, 0, p;\n\t}"
        : "=r"(done) : "r"(mbar), "r"(parity) : "memory");
    if (!done) {
        asm volatile(
            "{\n\t.reg .pred P1;\n\t"
            "W%=:\n\t"
            "mbarrier.try_wait.parity.acquire.cta.shared::cta.b64 P1, [%0], %1, 0x989680;\n\t"
            "@P1 bra.uni D%=;\n\t"
            "bra.uni W%=;\n\t"
            "D%=:\n\t}"
            :: "r"(mbar), "r"(parity) : "memory");
    }
}

__global__ void __launch_bounds__(THREADS) matcher_cost_kernel(
    const float*  __restrict__ logits,   // (B,Q,K)
    const float4* __restrict__ pboxes,   // (B,Q,4)
    const int*    __restrict__ labels,   // (B,N)
    const float4* __restrict__ tboxes,   // (B,N,4)
    float* __restrict__ out)             // (B,Q,N)
{
    __shared__ float s_buf[WARPS][2][BUF_FLOATS];        // 38,912 B
    __shared__ alignas(8) unsigned long long s_mbar[WARPS][2];

    const int tid  = threadIdx.x;
    const int w    = tid >> 5;
    const int lane = tid & 31;

    if (tid < WARPS * 2)
        mbar_init(smem_u32(&s_mbar[tid >> 1][tid & 1]), 1);
    asm volatile("fence.proxy.async.shared::cta;" ::: "memory");
    __syncthreads();

    const int  g    = blockIdx.x * WARPS + w;   // global warp id
    const long row0 = (long)g * RPW;
    const char* gbase = (const char*)logits;

    const uint32_t mb0 = smem_u32(&s_mbar[w][0]);
    const uint32_t mb1 = smem_u32(&s_mbar[w][1]);
    const uint32_t sb0 = smem_u32(&s_buf[w][0][0]);
    const uint32_t sb1 = smem_u32(&s_buf[w][1][0]);

    // Prime the pipeline: rows row0, row0+1.
    if (lane == 0) {
        issue_row_copy(sb0, gbase, row0,     mb0);
        issue_row_copy(sb1, gbase, row0 + 1, mb1);
    }

    #pragma unroll 1
    for (int r = 0; r < RPW; r++) {
        const long row = row0 + r;
        const int  s   = r & 1;
        const uint32_t mbar = s ? mb1 : mb0;
        const float* sbuf   = s_buf[w][s];

        mbar_wait(mbar, (uint32_t)(r >> 1));

        const int head4 = (int)((row * (long)ROW_BYTES) & 15L) >> 2; // float offset
        const float* rdata = sbuf + head4;

        const int b = (int)(row / QQ);
        const int bn0 = b * NN;

        const float4 pb = pboxes[row];
        const float px0 = pb.x - 0.5f * pb.z, px1 = pb.x + 0.5f * pb.z;
        const float py0 = pb.y - 0.5f * pb.w, py1 = pb.y + 0.5f * pb.w;
        const float area1 = pb.z * pb.w;
        float* const orow = out + row * NN;

        #pragma unroll
        for (int i = 0; i < 4; i++) {
            int n = lane + i * 32;
            if (n < NN) {
                int lab = __ldg(labels + bn0 + n);
                lab = min(max(lab, 0), KK - 1);
                float x = rdata[lab];             // LDS select

                // focal class cost (3 MUFU)
                float e  = __expf(-x);
                float sg = 1.0f + e;
                float p  = __fdividef(1.0f, sg);
                float L  = __logf(sg);
                float logp   = fmaxf(-L,     -18.420681f);
                float log1mp = fmaxf(-x - L, -18.420681f);
                float omp = 1.0f - p;
                float cls = -0.25f * omp * omp * logp + 0.75f * p * p * log1mp;

                // L1 box cost
                float4 tb = __ldg(tboxes + bn0 + n);
                float l1 = fabsf(pb.x - tb.x) + fabsf(pb.y - tb.y)
                         + fabsf(pb.z - tb.z) + fabsf(pb.w - tb.w);

                // GIoU (1 MUFU)
                float tx0 = tb.x - 0.5f * tb.z, tx1 = tb.x + 0.5f * tb.z;
                float ty0 = tb.y - 0.5f * tb.w, ty1 = tb.y + 0.5f * tb.w;
                float area2 = tb.z * tb.w;
                float wi = fmaxf(fminf(px1, tx1) - fmaxf(px0, tx0), 0.0f);
                float hi = fmaxf(fminf(py1, ty1) - fmaxf(py0, ty0), 0.0f);
                float inter = wi * hi;
                float uni   = area1 + area2 - inter;
                float wc = fmaxf(px1, tx1) - fminf(px0, tx0);
                float hc = fmaxf(py1, ty1) - fminf(py0, ty0);
                float ac = wc * hc;
                float num  = ac * (inter - uni) + uni * uni;
                float giou = num * __fdividef(1.0f, uni * ac);

                orow[n] = 2.0f * cls + 5.0f * l1 - 2.0f * giou;
            }
        }

        // Recycle this buffer for row r+2.
        if (r + 2 < RPW) {
            __syncwarp();
            if (lane == 0) {
                asm volatile("fence.proxy.async.shared::cta;" ::: "memory");
                issue_row_copy(s ? sb1 : sb0, gbase, row + 2, mbar);
            }
        }
    }
}

extern "C" void kernel_launch(void* const* d_in, const int* in_sizes, int n_in,
                              void* d_out, int out_size)
{
    const float*  logits = (const float*)d_in[0];
    const float4* pboxes = (const float4*)d_in[1];
    const int*    labels = (const int*)d_in[2];
    const float4* tboxes = (const float4*)d_in[3];
    float* out = (float*)d_out;

    matcher_cost_kernel<<<BLOCKS, THREADS>>>(logits, pboxes, labels, tboxes, out);
}